// round 15
// baseline (speedup 1.0000x reference)
#include <cuda_runtime.h>
#include <cuda_bf16.h>
#include <math.h>
#include <stdint.h>

#define NN 64
#define CC 512
#define HWD 1024
#define KK 64
#define ALPHA 50.0f
#define EPSV 1e-12f

// ---- device scratch ----
__device__ __nv_bfloat16 g_WnT_hi[KK * CC], g_WnT_lo[KK * CC];   // [k][c]
__device__ float g_inv[NN * HWD];
__device__ __nv_bfloat16 g_saT_hi[(size_t)NN * KK * HWD];        // [n][k][h]
__device__ __nv_bfloat16 g_saT_lo[(size_t)NN * KK * HWD];
__device__ float g_psum[NN * KK * 8];
__device__ float g_vlad[(size_t)NN * KK * CC];

// ---- smem layout (bytes). Pitch 144B = 72 bf16 per row. (R9 layout) ----
#define SM_AHI 0
#define SM_ALO 18432
#define SM_BHI 36864
#define SM_BLO 46080
#define SM_AUX 55296            // bias / asum
#define SM_SINV 55552
#define SM_RED 56064
#define SMEM_BYTES 57344
#define PITCHB 144

__device__ __forceinline__ uint32_t smem_u32(const void* p) {
    uint32_t a;
    asm("{ .reg .u64 t; cvta.to.shared.u64 t, %1; cvt.u32.u64 %0, t; }" : "=r"(a) : "l"(p));
    return a;
}
__device__ __forceinline__ void ldm4(uint32_t* r, uint32_t addr) {
    asm volatile("ldmatrix.sync.aligned.m8n8.x4.shared.b16 {%0,%1,%2,%3}, [%4];"
                 : "=r"(r[0]), "=r"(r[1]), "=r"(r[2]), "=r"(r[3]) : "r"(addr));
}
__device__ __forceinline__ void mma16816(float* d, const uint32_t* a, const uint32_t* b) {
    asm volatile(
        "mma.sync.aligned.m16n8k16.row.col.f32.bf16.bf16.f32 "
        "{%0,%1,%2,%3}, {%4,%5,%6,%7}, {%8,%9}, {%0,%1,%2,%3};"
        : "+f"(d[0]), "+f"(d[1]), "+f"(d[2]), "+f"(d[3])
        : "r"(a[0]), "r"(a[1]), "r"(a[2]), "r"(a[3]), "r"(b[0]), "r"(b[1]));
}

union B8 { uint4 u; __nv_bfloat162 b[4]; };

__device__ __forceinline__ void split8(float4 v0, float4 v1, B8& H, B8& L) {
    H.b[0] = __floats2bfloat162_rn(v0.x, v0.y);
    H.b[1] = __floats2bfloat162_rn(v0.z, v0.w);
    H.b[2] = __floats2bfloat162_rn(v1.x, v1.y);
    H.b[3] = __floats2bfloat162_rn(v1.z, v1.w);
    L.b[0] = __floats2bfloat162_rn(v0.x - __low2float(H.b[0]), v0.y - __high2float(H.b[0]));
    L.b[1] = __floats2bfloat162_rn(v0.z - __low2float(H.b[1]), v0.w - __high2float(H.b[1]));
    L.b[2] = __floats2bfloat162_rn(v1.x - __low2float(H.b[2]), v1.y - __high2float(H.b[2]));
    L.b[3] = __floats2bfloat162_rn(v1.z - __low2float(H.b[3]), v1.w - __high2float(H.b[3]));
}

// ---------------- kernel 1: normalize W columns -> bf16 hi/lo W^T ----------------
__global__ __launch_bounds__(256) void kWnorm(const float* __restrict__ w) {
    __shared__ float part[4][64];
    int t = threadIdx.x;
    int k = t & 63, p = t >> 6;
    float s = 0.f;
    for (int c = p; c < CC; c += 4) { float v = w[c * KK + k]; s += v * v; }
    part[p][k] = s;
    __syncthreads();
    if (p == 0) {
        float tot = part[0][k] + part[1][k] + part[2][k] + part[3][k];
        part[0][k] = 1.f / fmaxf(sqrtf(tot), EPSV);
    }
    __syncthreads();
    float inv = part[0][k];
    for (int c = p; c < CC; c += 4) {
        float v = w[c * KK + k] * inv;
        __nv_bfloat16 hh = __float2bfloat16(v);
        __nv_bfloat16 ll = __float2bfloat16(v - __bfloat162float(hh));
        g_WnT_hi[k * CC + c] = hh;
        g_WnT_lo[k * CC + c] = ll;
    }
}

// ---------------- kernel 2: FUSED norm + feature + logits GEMM + softmax ----------------
__global__ __launch_bounds__(256, 3) void kLogitsFused(const float* __restrict__ x,
                                                       const float* __restrict__ bias,
                                                       float* __restrict__ feat,
                                                       float* __restrict__ sa_raw) {
    extern __shared__ char sm[];
    uint32_t sb = smem_u32(sm);
    int t = threadIdx.x, wid = t >> 5, l = t & 31;
    int n = blockIdx.y, hb = blockIdx.x * 128;
    float* sbias = (float*)(sm + SM_AUX);
    float* sinv = (float*)(sm + SM_SINV);
    float* red = (float*)(sm + SM_RED);
    if (t < 64) sbias[t] = bias[t];

    int h = t & 127, half = t >> 7;

    // ---- phase 1: per-pixel inv L2 norm ----
    {
        const float* xp = x + ((size_t)n * CC + half * 256) * HWD + hb + h;
        float s = 0.f;
#pragma unroll 8
        for (int i = 0; i < 256; i++) { float v = xp[(size_t)i * HWD]; s += v * v; }
        red[t] = s;
    }
    __syncthreads();
    if (t < 128) {
        float iv = 1.f / fmaxf(sqrtf(red[t] + red[t + 128]), EPSV);
        sinv[t] = iv;
        g_inv[n * HWD + hb + t] = iv;
    }
    __syncthreads();

    // ---- phase 2: GEMM over 8 chunks of 64 c ----
    int mh = (wid & 3) * 32, nk = (wid >> 2) * 32;
    int arow = (l & 7) + ((l >> 3) & 1) * 8, acol = (l >> 4) * 8;
    int brow = (l & 7) + ((l >> 4) & 1) * 8, bcol = ((l >> 3) & 1) * 8;
    uint32_t aHiA = sb + SM_AHI + (mh + arow) * PITCHB + acol * 2;
    uint32_t aLoA = sb + SM_ALO + (mh + arow) * PITCHB + acol * 2;
    uint32_t bHiA = sb + SM_BHI + (nk + brow) * PITCHB + bcol * 2;
    uint32_t bLoA = sb + SM_BLO + (nk + brow) * PITCHB + bcol * 2;

    float acc[2][4][4];
#pragma unroll
    for (int i = 0; i < 2; i++)
#pragma unroll
        for (int j = 0; j < 4; j++)
#pragma unroll
            for (int q = 0; q < 4; q++) acc[i][j][q] = 0.f;

    const float* xcol = x + (size_t)n * CC * HWD + hb + h;
    int sbr = t >> 2, sbs = (t & 3) * 16;
    int fh0 = t >> 2, fcseg = (t & 3) * 4;
    float* fbase = feat + ((size_t)(n * HWD + hb)) * CC;

    for (int cb = 0; cb < CC; cb += 64) {
        __syncthreads();
        {   // stage A
            float iv = sinv[h];
#pragma unroll
            for (int q = 0; q < 4; q++) {
                int c0 = cb + half * 32 + q * 8;
                float4 v0, v1;
                v0.x = xcol[(size_t)(c0 + 0) * HWD] * iv;
                v0.y = xcol[(size_t)(c0 + 1) * HWD] * iv;
                v0.z = xcol[(size_t)(c0 + 2) * HWD] * iv;
                v0.w = xcol[(size_t)(c0 + 3) * HWD] * iv;
                v1.x = xcol[(size_t)(c0 + 4) * HWD] * iv;
                v1.y = xcol[(size_t)(c0 + 5) * HWD] * iv;
                v1.z = xcol[(size_t)(c0 + 6) * HWD] * iv;
                v1.w = xcol[(size_t)(c0 + 7) * HWD] * iv;
                B8 H, L;
                split8(v0, v1, H, L);
                uint32_t off = h * PITCHB + (half * 32 + q * 8) * 2;
                *(uint4*)(sm + SM_AHI + off) = H.u;
                *(uint4*)(sm + SM_ALO + off) = L.u;
            }
        }
        {   // stage B
            const uint4* sh = (const uint4*)(g_WnT_hi + sbr * CC + cb + sbs);
            const uint4* sl = (const uint4*)(g_WnT_lo + sbr * CC + cb + sbs);
            uint4 h0 = sh[0], h1 = sh[1], l0 = sl[0], l1 = sl[1];
            uint32_t off = sbr * PITCHB + sbs * 2;
            *(uint4*)(sm + SM_BHI + off) = h0;
            *(uint4*)(sm + SM_BHI + off + 16) = h1;
            *(uint4*)(sm + SM_BLO + off) = l0;
            *(uint4*)(sm + SM_BLO + off + 16) = l1;
        }
        __syncthreads();
#pragma unroll
        for (int kb = 0; kb < 4; kb++) {
            uint32_t ah[2][4], al[2][4];
#pragma unroll
            for (int m2 = 0; m2 < 2; m2++) {
                ldm4(ah[m2], aHiA + m2 * 16 * PITCHB + kb * 32);
                ldm4(al[m2], aLoA + m2 * 16 * PITCHB + kb * 32);
            }
#pragma unroll
            for (int np = 0; np < 2; np++) {
                uint32_t bh[4], bl[4];
                ldm4(bh, bHiA + np * 16 * PITCHB + kb * 32);
                ldm4(bl, bLoA + np * 16 * PITCHB + kb * 32);
#pragma unroll
                for (int m2 = 0; m2 < 2; m2++)
#pragma unroll
                    for (int hf = 0; hf < 2; hf++) {
                        float* d = acc[m2][np * 2 + hf];
                        mma16816(d, ah[m2], bh + hf * 2);
                        mma16816(d, ah[m2], bl + hf * 2);
                        mma16816(d, al[m2], bh + hf * 2);
                    }
            }
        }
        // feat writeout: fp32 = hi + lo from A smem
#pragma unroll
        for (int pass = 0; pass < 2; pass++) {
            int fh = fh0 + pass * 64;
#pragma unroll
            for (int i = 0; i < 4; i++) {
                int c = fcseg + i * 16;
                uint2 uh = *(uint2*)(sm + SM_AHI + fh * PITCHB + c * 2);
                uint2 ul = *(uint2*)(sm + SM_ALO + fh * PITCHB + c * 2);
                __nv_bfloat162 h0 = *(__nv_bfloat162*)&uh.x, h1 = *(__nv_bfloat162*)&uh.y;
                __nv_bfloat162 l0 = *(__nv_bfloat162*)&ul.x, l1 = *(__nv_bfloat162*)&ul.y;
                float4 o;
                o.x = __low2float(h0) + __low2float(l0);
                o.y = __high2float(h0) + __high2float(l0);
                o.z = __low2float(h1) + __low2float(l1);
                o.w = __high2float(h1) + __high2float(l1);
                *(float4*)(fbase + (size_t)fh * CC + cb + c) = o;
            }
        }
    }
    __syncthreads();
    // ---- epilogue ----
    float* Ls = (float*)sm;
    int rr = l >> 2, c2 = (l & 3) * 2;
#pragma unroll
    for (int m2 = 0; m2 < 2; m2++)
#pragma unroll
        for (int nb = 0; nb < 4; nb++) {
            float* d = acc[m2][nb];
            int h0 = mh + m2 * 16 + rr, k0 = nk + nb * 8 + c2;
            Ls[k0 * 129 + h0] = d[0];
            Ls[(k0 + 1) * 129 + h0] = d[1];
            Ls[k0 * 129 + h0 + 8] = d[2];
            Ls[(k0 + 1) * 129 + h0 + 8] = d[3];
        }
    __syncthreads();
    {
        float* sp = sa_raw + ((size_t)n * KK) * HWD + hb;
        int h2 = t & 127, kh = t >> 7;
#pragma unroll
        for (int r = 0; r < 32; r++) {
            int k = r * 2 + kh;
            sp[(size_t)k * HWD + h2] = Ls[k * 129 + h2];
        }
    }
    __syncthreads();
    if (t < 128) {
        float m = -1e30f;
#pragma unroll
        for (int k = 0; k < 64; k++)
            m = fmaxf(m, (Ls[k * 129 + t] + sbias[k]) * ALPHA);
        float s = 0.f;
#pragma unroll
        for (int k = 0; k < 64; k++) {
            float e = __expf((Ls[k * 129 + t] + sbias[k]) * ALPHA - m);
            s += e;
            Ls[k * 129 + t] = e;
        }
        float r = 1.f / s;
#pragma unroll
        for (int k = 0; k < 64; k++) Ls[k * 129 + t] *= r;
    }
    __syncthreads();
    {
        int h2 = t & 127, kh = t >> 7;
        __nv_bfloat16* gh = g_saT_hi + ((size_t)n * KK) * HWD + hb;
        __nv_bfloat16* gl = g_saT_lo + ((size_t)n * KK) * HWD + hb;
#pragma unroll
        for (int r = 0; r < 32; r++) {
            int k = r * 2 + kh;
            float v = Ls[k * 129 + h2];
            __nv_bfloat16 hh = __float2bfloat16(v);
            __nv_bfloat16 ll = __float2bfloat16(v - __bfloat162float(hh));
            gh[(size_t)k * HWD + h2] = hh;
            gl[(size_t)k * HWD + h2] = ll;
        }
    }
    if (t < 64) {
        float s = 0.f;
#pragma unroll
        for (int hq = 0; hq < 128; hq++) s += Ls[t * 129 + hq];
        g_psum[(n * KK + t) * 8 + blockIdx.x] = s;
    }
}

// ---------------- kernel 3: vlad GEMM via mma.sync (asum folded) ----------------
__global__ __launch_bounds__(256, 3) void kVladMMA(const float* __restrict__ x,
                                                   const float* __restrict__ w) {
    extern __shared__ char sm[];
    uint32_t sb = smem_u32(sm);
    int t = threadIdx.x, wid = t >> 5, l = t & 31;
    int n = blockIdx.y, cb = blockIdx.x * 128;
    float* sas = (float*)(sm + SM_AUX);
    if (t < 64) {
        const float* p = g_psum + (size_t)(n * KK + t) * 8;
        float s = 0.f;
#pragma unroll
        for (int i = 0; i < 8; i++) s += p[i];
        sas[t] = s;
    }

    int mh = (wid & 3) * 32, nk = (wid >> 2) * 32;
    int arow = (l & 7) + ((l >> 3) & 1) * 8, acol = (l >> 4) * 8;
    int brow = (l & 7) + ((l >> 4) & 1) * 8, bcol = ((l >> 3) & 1) * 8;
    uint32_t aHiA = sb + SM_AHI + (mh + arow) * PITCHB + acol * 2;
    uint32_t aLoA = sb + SM_ALO + (mh + arow) * PITCHB + acol * 2;
    uint32_t bHiA = sb + SM_BHI + (nk + brow) * PITCHB + bcol * 2;
    uint32_t bLoA = sb + SM_BLO + (nk + brow) * PITCHB + bcol * 2;

    float acc[2][4][4];
#pragma unroll
    for (int i = 0; i < 2; i++)
#pragma unroll
        for (int j = 0; j < 4; j++)
#pragma unroll
            for (int q = 0; q < 4; q++) acc[i][j][q] = 0.f;

    int srow = t >> 1, scs = (t & 1) * 32;
    int sbr = t >> 2, sbs = (t & 3) * 16;
    const float* xb = x + ((size_t)(n * CC + cb)) * HWD;
    const float* ivb = g_inv + n * HWD;
    const __nv_bfloat16* shb = g_saT_hi + ((size_t)n * KK) * HWD;
    const __nv_bfloat16* slb = g_saT_lo + ((size_t)n * KK) * HWD;

    for (int hbk = 0; hbk < HWD; hbk += 64) {
        __syncthreads();
        {   // stage A: xn^T [c=128][h=64]
            const float4* src = (const float4*)(xb + (size_t)srow * HWD + hbk + scs);
            const float4* ivs = (const float4*)(ivb + hbk + scs);
#pragma unroll
            for (int q = 0; q < 4; q++) {
                float4 v0 = src[2 * q], v1 = src[2 * q + 1];
                float4 i0 = ivs[2 * q], i1 = ivs[2 * q + 1];
                v0.x *= i0.x; v0.y *= i0.y; v0.z *= i0.z; v0.w *= i0.w;
                v1.x *= i1.x; v1.y *= i1.y; v1.z *= i1.z; v1.w *= i1.w;
                B8 H, L;
                split8(v0, v1, H, L);
                uint32_t off = srow * PITCHB + scs * 2 + q * 16;
                *(uint4*)(sm + SM_AHI + off) = H.u;
                *(uint4*)(sm + SM_ALO + off) = L.u;
            }
        }
        {   // stage B: saT hi/lo passthrough
            const uint4* sh = (const uint4*)(shb + (size_t)sbr * HWD + hbk + sbs);
            const uint4* sl = (const uint4*)(slb + (size_t)sbr * HWD + hbk + sbs);
            uint4 h0 = sh[0], h1 = sh[1], l0 = sl[0], l1 = sl[1];
            uint32_t off = sbr * PITCHB + sbs * 2;
            *(uint4*)(sm + SM_BHI + off) = h0;
            *(uint4*)(sm + SM_BHI + off + 16) = h1;
            *(uint4*)(sm + SM_BLO + off) = l0;
            *(uint4*)(sm + SM_BLO + off + 16) = l1;
        }
        __syncthreads();
#pragma unroll
        for (int kb = 0; kb < 4; kb++) {
            uint32_t ah[2][4], al[2][4];
#pragma unroll
            for (int m2 = 0; m2 < 2; m2++) {
                ldm4(ah[m2], aHiA + m2 * 16 * PITCHB + kb * 32);
                ldm4(al[m2], aLoA + m2 * 16 * PITCHB + kb * 32);
            }
#pragma unroll
            for (int np = 0; np < 2; np++) {
                uint32_t bh[4], bl[4];
                ldm4(bh, bHiA + np * 16 * PITCHB + kb * 32);
                ldm4(bl, bLoA + np * 16 * PITCHB + kb * 32);
#pragma unroll
                for (int m2 = 0; m2 < 2; m2++)
#pragma unroll
                    for (int hf = 0; hf < 2; hf++) {
                        float* d = acc[m2][np * 2 + hf];
                        mma16816(d, ah[m2], bh + hf * 2);
                        mma16816(d, ah[m2], bl + hf * 2);
                        mma16816(d, al[m2], bh + hf * 2);
                    }
            }
        }
    }
    __syncthreads();
    float* Ts = (float*)sm;   // [k=64][129] holding D^T
    int rr = l >> 2, c2 = (l & 3) * 2;
#pragma unroll
    for (int m2 = 0; m2 < 2; m2++)
#pragma unroll
        for (int nb = 0; nb < 4; nb++) {
            float* d = acc[m2][nb];
            int c0 = mh + m2 * 16 + rr, k0 = nk + nb * 8 + c2;
            Ts[k0 * 129 + c0] = d[0];
            Ts[(k0 + 1) * 129 + c0] = d[1];
            Ts[k0 * 129 + c0 + 8] = d[2];
            Ts[(k0 + 1) * 129 + c0 + 8] = d[3];
        }
    __syncthreads();
    {
        int cc2 = t & 127, kh = t >> 7;
        float* vb = g_vlad + ((size_t)n * KK) * CC + cb;
        const float* wrow = w + (size_t)(cb + cc2) * KK;
#pragma unroll
        for (int r = 0; r < 32; r++) {
            int k = r * 2 + kh;
            vb[(size_t)k * CC + cc2] = Ts[k * 129 + cc2] - sas[k] * wrow[k];
        }
    }
}

// ---------------- kernel 4: intra-normalize vlad rows -> output ----------------
__global__ __launch_bounds__(128) void kVnorm(float* __restrict__ out) {
    __shared__ float red[4];
    __shared__ float sinv;
    int row = blockIdx.x;
    const float* p = g_vlad + (size_t)row * CC;
    int t = threadIdx.x;
    float v[4];
    float s = 0.f;
#pragma unroll
    for (int j = 0; j < 4; j++) { v[j] = p[t + j * 128]; s += v[j] * v[j]; }
#pragma unroll
    for (int o = 16; o > 0; o >>= 1) s += __shfl_xor_sync(0xffffffffu, s, o);
    int wq = t >> 5;
    if ((t & 31) == 0) red[wq] = s;
    __syncthreads();
    if (t == 0) sinv = 1.f / fmaxf(sqrtf(red[0] + red[1] + red[2] + red[3]), EPSV);
    __syncthreads();
    float inv = sinv;
    float* o = out + (size_t)row * CC;
#pragma unroll
    for (int j = 0; j < 4; j++) o[t + j * 128] = v[j] * inv;
}

extern "C" void kernel_launch(void* const* d_in, const int* in_sizes, int n_in,
                              void* d_out, int out_size) {
    const float* x = (const float*)d_in[0];     // [N,C,H,W]
    const float* w = (const float*)d_in[1];     // [C,K]
    const float* b = (const float*)d_in[2];     // [K]
    float* out = (float*)d_out;

    const size_t VLAD_OFF = 0;
    const size_t SA_OFF = (size_t)NN * KK * CC;
    const size_t FEAT_OFF = SA_OFF + (size_t)NN * KK * HWD;

    cudaFuncSetAttribute(kLogitsFused, cudaFuncAttributeMaxDynamicSharedMemorySize, SMEM_BYTES);
    cudaFuncSetAttribute(kVladMMA, cudaFuncAttributeMaxDynamicSharedMemorySize, SMEM_BYTES);

    kWnorm<<<1, 256>>>(w);
    kLogitsFused<<<dim3(HWD / 128, NN), 256, SMEM_BYTES>>>(x, b, out + FEAT_OFF, out + SA_OFF);
    kVladMMA<<<dim3(CC / 128, NN), 256, SMEM_BYTES>>>(x, w);
    kVnorm<<<NN * KK, 128>>>(out + VLAD_OFF);
}

// round 16
// speedup vs baseline: 1.2149x; 1.2149x over previous
#include <cuda_runtime.h>
#include <cuda_bf16.h>
#include <math.h>
#include <stdint.h>

#define NN 64
#define CC 512
#define HWD 1024
#define KK 64
#define ALPHA 50.0f
#define EPSV 1e-12f

// ---- device scratch ----
__device__ __nv_bfloat16 g_WnT_hi[KK * CC], g_WnT_lo[KK * CC];   // [k][c]
__device__ float g_inv[NN * HWD];
__device__ __nv_bfloat16 g_saT_hi[(size_t)NN * KK * HWD];        // [n][k][h]
__device__ __nv_bfloat16 g_saT_lo[(size_t)NN * KK * HWD];
__device__ float g_psum[NN * KK * 8];
__device__ float g_vlad[(size_t)NN * KK * CC];

// ---- smem layout (bytes). Pitch 144B = 72 bf16 per row. (R9 layout) ----
#define SM_AHI 0
#define SM_ALO 18432
#define SM_BHI 36864
#define SM_BLO 46080
#define SM_AUX 55296            // bias / asum
#define SM_SINV 55552
#define SM_RED 56064            // 2KB (512 floats)
#define SMEM_BYTES 58368
#define PITCHB 144

__device__ __forceinline__ uint32_t smem_u32(const void* p) {
    uint32_t a;
    asm("{ .reg .u64 t; cvta.to.shared.u64 t, %1; cvt.u32.u64 %0, t; }" : "=r"(a) : "l"(p));
    return a;
}
__device__ __forceinline__ void ldm4(uint32_t* r, uint32_t addr) {
    asm volatile("ldmatrix.sync.aligned.m8n8.x4.shared.b16 {%0,%1,%2,%3}, [%4];"
                 : "=r"(r[0]), "=r"(r[1]), "=r"(r[2]), "=r"(r[3]) : "r"(addr));
}
__device__ __forceinline__ void mma16816(float* d, const uint32_t* a, const uint32_t* b) {
    asm volatile(
        "mma.sync.aligned.m16n8k16.row.col.f32.bf16.bf16.f32 "
        "{%0,%1,%2,%3}, {%4,%5,%6,%7}, {%8,%9}, {%0,%1,%2,%3};"
        : "+f"(d[0]), "+f"(d[1]), "+f"(d[2]), "+f"(d[3])
        : "r"(a[0]), "r"(a[1]), "r"(a[2]), "r"(a[3]), "r"(b[0]), "r"(b[1]));
}

union B8 { uint4 u; __nv_bfloat162 b[4]; };

__device__ __forceinline__ void split8(float4 v0, float4 v1, B8& H, B8& L) {
    H.b[0] = __floats2bfloat162_rn(v0.x, v0.y);
    H.b[1] = __floats2bfloat162_rn(v0.z, v0.w);
    H.b[2] = __floats2bfloat162_rn(v1.x, v1.y);
    H.b[3] = __floats2bfloat162_rn(v1.z, v1.w);
    L.b[0] = __floats2bfloat162_rn(v0.x - __low2float(H.b[0]), v0.y - __high2float(H.b[0]));
    L.b[1] = __floats2bfloat162_rn(v0.z - __low2float(H.b[1]), v0.w - __high2float(H.b[1]));
    L.b[2] = __floats2bfloat162_rn(v1.x - __low2float(H.b[2]), v1.y - __high2float(H.b[2]));
    L.b[3] = __floats2bfloat162_rn(v1.z - __low2float(H.b[3]), v1.w - __high2float(H.b[3]));
}

// ---------------- kernel 1: normalize W columns -> bf16 hi/lo W^T ----------------
__global__ __launch_bounds__(256) void kWnorm(const float* __restrict__ w) {
    __shared__ float part[4][64];
    int t = threadIdx.x;
    int k = t & 63, p = t >> 6;
    float s = 0.f;
    for (int c = p; c < CC; c += 4) { float v = w[c * KK + k]; s += v * v; }
    part[p][k] = s;
    __syncthreads();
    if (p == 0) {
        float tot = part[0][k] + part[1][k] + part[2][k] + part[3][k];
        part[0][k] = 1.f / fmaxf(sqrtf(tot), EPSV);
    }
    __syncthreads();
    float inv = part[0][k];
    for (int c = p; c < CC; c += 4) {
        float v = w[c * KK + k] * inv;
        __nv_bfloat16 hh = __float2bfloat16(v);
        __nv_bfloat16 ll = __float2bfloat16(v - __bfloat162float(hh));
        g_WnT_hi[k * CC + c] = hh;
        g_WnT_lo[k * CC + c] = ll;
    }
}

// ---------------- kernel 2: FUSED norm + feature + logits, 512 threads ----------------
__global__ __launch_bounds__(512, 2) void kLogitsFused(const float* __restrict__ x,
                                                       const float* __restrict__ bias,
                                                       float* __restrict__ feat,
                                                       float* __restrict__ sa_raw) {
    extern __shared__ char sm[];
    uint32_t sb = smem_u32(sm);
    int t = threadIdx.x, wid = t >> 5, l = t & 31;
    int n = blockIdx.y, hb = blockIdx.x * 128;
    float* sbias = (float*)(sm + SM_AUX);
    float* sinv = (float*)(sm + SM_SINV);
    float* red = (float*)(sm + SM_RED);
    if (t < 64) sbias[t] = bias[t];

    int h = t & 127, q4 = t >> 7;   // q4: 0..3

    // ---- phase 1: per-pixel inv L2 norm (each thread: 128 c's) ----
    {
        const float* xp = x + ((size_t)n * CC + q4 * 128) * HWD + hb + h;
        float s = 0.f;
#pragma unroll 8
        for (int i = 0; i < 128; i++) { float v = xp[(size_t)i * HWD]; s += v * v; }
        red[t] = s;
    }
    __syncthreads();
    if (t < 128) {
        float iv = 1.f / fmaxf(sqrtf(red[t] + red[t + 128] + red[t + 256] + red[t + 384]), EPSV);
        sinv[t] = iv;
        g_inv[n * HWD + hb + t] = iv;
    }
    __syncthreads();

    // ---- phase 2: GEMM over 8 chunks of 64 c ----
    int mh = (wid & 7) * 16, nk = (wid >> 3) * 32;
    int arow = (l & 7) + ((l >> 3) & 1) * 8, acol = (l >> 4) * 8;
    int brow = (l & 7) + ((l >> 4) & 1) * 8, bcol = ((l >> 3) & 1) * 8;
    uint32_t aHiA = sb + SM_AHI + (mh + arow) * PITCHB + acol * 2;
    uint32_t aLoA = sb + SM_ALO + (mh + arow) * PITCHB + acol * 2;
    uint32_t bHiA = sb + SM_BHI + (nk + brow) * PITCHB + bcol * 2;
    uint32_t bLoA = sb + SM_BLO + (nk + brow) * PITCHB + bcol * 2;

    float acc[4][4];
#pragma unroll
    for (int j = 0; j < 4; j++)
#pragma unroll
        for (int q = 0; q < 4; q++) acc[j][q] = 0.f;

    const float* xcol = x + (size_t)n * CC * HWD + hb + h;
    int sbr = t >> 3, sbs = (t & 7) * 8;   // B stage: 64 rows, 8 c's (16B) each
    int fh0 = t >> 2, fcseg = (t & 3) * 4; // feat writeout
    float* fbase = feat + ((size_t)(n * HWD + hb)) * CC;

    for (int cb = 0; cb < CC; cb += 64) {
        __syncthreads();
        {   // stage A: thread covers h, c = cb + q4*16 .. +16
            float iv = sinv[h];
#pragma unroll
            for (int q = 0; q < 2; q++) {
                int c0 = cb + q4 * 16 + q * 8;
                float4 v0, v1;
                v0.x = xcol[(size_t)(c0 + 0) * HWD] * iv;
                v0.y = xcol[(size_t)(c0 + 1) * HWD] * iv;
                v0.z = xcol[(size_t)(c0 + 2) * HWD] * iv;
                v0.w = xcol[(size_t)(c0 + 3) * HWD] * iv;
                v1.x = xcol[(size_t)(c0 + 4) * HWD] * iv;
                v1.y = xcol[(size_t)(c0 + 5) * HWD] * iv;
                v1.z = xcol[(size_t)(c0 + 6) * HWD] * iv;
                v1.w = xcol[(size_t)(c0 + 7) * HWD] * iv;
                B8 H, L;
                split8(v0, v1, H, L);
                uint32_t off = h * PITCHB + (q4 * 16 + q * 8) * 2;
                *(uint4*)(sm + SM_AHI + off) = H.u;
                *(uint4*)(sm + SM_ALO + off) = L.u;
            }
        }
        {   // stage B: 1 uint4 per hi/lo
            const uint4* sh = (const uint4*)(g_WnT_hi + sbr * CC + cb + sbs);
            const uint4* sl = (const uint4*)(g_WnT_lo + sbr * CC + cb + sbs);
            uint4 h0 = sh[0], l0 = sl[0];
            uint32_t off = sbr * PITCHB + sbs * 2;
            *(uint4*)(sm + SM_BHI + off) = h0;
            *(uint4*)(sm + SM_BLO + off) = l0;
        }
        __syncthreads();
#pragma unroll
        for (int kb = 0; kb < 4; kb++) {
            uint32_t ah[4], al[4];
            ldm4(ah, aHiA + kb * 32);
            ldm4(al, aLoA + kb * 32);
#pragma unroll
            for (int np = 0; np < 2; np++) {
                uint32_t bh[4], bl[4];
                ldm4(bh, bHiA + np * 16 * PITCHB + kb * 32);
                ldm4(bl, bLoA + np * 16 * PITCHB + kb * 32);
#pragma unroll
                for (int hf = 0; hf < 2; hf++) {
                    float* d = acc[np * 2 + hf];
                    mma16816(d, ah, bh + hf * 2);
                    mma16816(d, ah, bl + hf * 2);
                    mma16816(d, al, bh + hf * 2);
                }
            }
        }
        // feat writeout: fp32 = hi + lo from A smem (each thread: 1 row, 16 c)
#pragma unroll
        for (int i = 0; i < 4; i++) {
            int c = fcseg + i * 16;
            uint2 uh = *(uint2*)(sm + SM_AHI + fh0 * PITCHB + c * 2);
            uint2 ul = *(uint2*)(sm + SM_ALO + fh0 * PITCHB + c * 2);
            __nv_bfloat162 h0 = *(__nv_bfloat162*)&uh.x, h1 = *(__nv_bfloat162*)&uh.y;
            __nv_bfloat162 l0 = *(__nv_bfloat162*)&ul.x, l1 = *(__nv_bfloat162*)&ul.y;
            float4 o;
            o.x = __low2float(h0) + __low2float(l0);
            o.y = __high2float(h0) + __high2float(l0);
            o.z = __low2float(h1) + __low2float(l1);
            o.w = __high2float(h1) + __high2float(l1);
            *(float4*)(fbase + (size_t)fh0 * CC + cb + c) = o;
        }
    }
    __syncthreads();
    // ---- epilogue: logits -> Ls[64][129] ----
    float* Ls = (float*)sm;
    int rr = l >> 2, c2 = (l & 3) * 2;
#pragma unroll
    for (int nb = 0; nb < 4; nb++) {
        float* d = acc[nb];
        int h0 = mh + rr, k0 = nk + nb * 8 + c2;
        Ls[k0 * 129 + h0] = d[0];
        Ls[(k0 + 1) * 129 + h0] = d[1];
        Ls[k0 * 129 + h0 + 8] = d[2];
        Ls[(k0 + 1) * 129 + h0 + 8] = d[3];
    }
    __syncthreads();
    {   // raw logits out
        float* sp = sa_raw + ((size_t)n * KK) * HWD + hb;
#pragma unroll
        for (int r = 0; r < 16; r++) {
            int k = r * 4 + q4;
            sp[(size_t)k * HWD + h] = Ls[k * 129 + h];
        }
    }
    __syncthreads();
    if (t < 128) {
        float m = -1e30f;
#pragma unroll
        for (int k = 0; k < 64; k++)
            m = fmaxf(m, (Ls[k * 129 + t] + sbias[k]) * ALPHA);
        float s = 0.f;
#pragma unroll
        for (int k = 0; k < 64; k++) {
            float e = __expf((Ls[k * 129 + t] + sbias[k]) * ALPHA - m);
            s += e;
            Ls[k * 129 + t] = e;
        }
        float r = 1.f / s;
#pragma unroll
        for (int k = 0; k < 64; k++) Ls[k * 129 + t] *= r;
    }
    __syncthreads();
    {   // soft-assign bf16 hi/lo
        __nv_bfloat16* gh = g_saT_hi + ((size_t)n * KK) * HWD + hb;
        __nv_bfloat16* gl = g_saT_lo + ((size_t)n * KK) * HWD + hb;
#pragma unroll
        for (int r = 0; r < 16; r++) {
            int k = r * 4 + q4;
            float v = Ls[k * 129 + h];
            __nv_bfloat16 hh = __float2bfloat16(v);
            __nv_bfloat16 ll = __float2bfloat16(v - __bfloat162float(hh));
            gh[(size_t)k * HWD + h] = hh;
            gl[(size_t)k * HWD + h] = ll;
        }
    }
    if (t < 64) {
        float s = 0.f;
#pragma unroll
        for (int hq = 0; hq < 128; hq++) s += Ls[t * 129 + hq];
        g_psum[(n * KK + t) * 8 + blockIdx.x] = s;
    }
}

// ---------------- kernel 3: vlad GEMM, 512 threads ----------------
__global__ __launch_bounds__(512, 2) void kVladMMA(const float* __restrict__ x,
                                                   const float* __restrict__ w) {
    extern __shared__ char sm[];
    uint32_t sb = smem_u32(sm);
    int t = threadIdx.x, wid = t >> 5, l = t & 31;
    int n = blockIdx.y, cb = blockIdx.x * 128;
    float* sas = (float*)(sm + SM_AUX);
    if (t < 64) {
        const float* p = g_psum + (size_t)(n * KK + t) * 8;
        float s = 0.f;
#pragma unroll
        for (int i = 0; i < 8; i++) s += p[i];
        sas[t] = s;
    }

    int mh = (wid & 7) * 16, nk = (wid >> 3) * 32;
    int arow = (l & 7) + ((l >> 3) & 1) * 8, acol = (l >> 4) * 8;
    int brow = (l & 7) + ((l >> 4) & 1) * 8, bcol = ((l >> 3) & 1) * 8;
    uint32_t aHiA = sb + SM_AHI + (mh + arow) * PITCHB + acol * 2;
    uint32_t aLoA = sb + SM_ALO + (mh + arow) * PITCHB + acol * 2;
    uint32_t bHiA = sb + SM_BHI + (nk + brow) * PITCHB + bcol * 2;
    uint32_t bLoA = sb + SM_BLO + (nk + brow) * PITCHB + bcol * 2;

    float acc[4][4];
#pragma unroll
    for (int j = 0; j < 4; j++)
#pragma unroll
        for (int q = 0; q < 4; q++) acc[j][q] = 0.f;

    int srow = t >> 2, scs = (t & 3) * 16;    // A stage: 128 rows, 16 h's each
    int sbr = t >> 3, sbs = (t & 7) * 8;      // B stage
    const float* xb = x + ((size_t)(n * CC + cb)) * HWD;
    const float* ivb = g_inv + n * HWD;
    const __nv_bfloat16* shb = g_saT_hi + ((size_t)n * KK) * HWD;
    const __nv_bfloat16* slb = g_saT_lo + ((size_t)n * KK) * HWD;

    for (int hbk = 0; hbk < HWD; hbk += 64) {
        __syncthreads();
        {   // stage A: xn^T [c=128][h=64], thread: 1 c-row, 16 h's
            const float4* src = (const float4*)(xb + (size_t)srow * HWD + hbk + scs);
            const float4* ivs = (const float4*)(ivb + hbk + scs);
#pragma unroll
            for (int q = 0; q < 2; q++) {
                float4 v0 = src[2 * q], v1 = src[2 * q + 1];
                float4 i0 = ivs[2 * q], i1 = ivs[2 * q + 1];
                v0.x *= i0.x; v0.y *= i0.y; v0.z *= i0.z; v0.w *= i0.w;
                v1.x *= i1.x; v1.y *= i1.y; v1.z *= i1.z; v1.w *= i1.w;
                B8 H, L;
                split8(v0, v1, H, L);
                uint32_t off = srow * PITCHB + scs * 2 + q * 16;
                *(uint4*)(sm + SM_AHI + off) = H.u;
                *(uint4*)(sm + SM_ALO + off) = L.u;
            }
        }
        {   // stage B: saT hi/lo passthrough
            const uint4* sh = (const uint4*)(shb + (size_t)sbr * HWD + hbk + sbs);
            const uint4* sl = (const uint4*)(slb + (size_t)sbr * HWD + hbk + sbs);
            uint4 h0 = sh[0], l0 = sl[0];
            uint32_t off = sbr * PITCHB + sbs * 2;
            *(uint4*)(sm + SM_BHI + off) = h0;
            *(uint4*)(sm + SM_BLO + off) = l0;
        }
        __syncthreads();
#pragma unroll
        for (int kb = 0; kb < 4; kb++) {
            uint32_t ah[4], al[4];
            ldm4(ah, aHiA + kb * 32);
            ldm4(al, aLoA + kb * 32);
#pragma unroll
            for (int np = 0; np < 2; np++) {
                uint32_t bh[4], bl[4];
                ldm4(bh, bHiA + np * 16 * PITCHB + kb * 32);
                ldm4(bl, bLoA + np * 16 * PITCHB + kb * 32);
#pragma unroll
                for (int hf = 0; hf < 2; hf++) {
                    float* d = acc[np * 2 + hf];
                    mma16816(d, ah, bh + hf * 2);
                    mma16816(d, ah, bl + hf * 2);
                    mma16816(d, al, bh + hf * 2);
                }
            }
        }
    }
    __syncthreads();
    float* Ts = (float*)sm;   // [k=64][129] holding D^T
    int rr = l >> 2, c2 = (l & 3) * 2;
#pragma unroll
    for (int nb = 0; nb < 4; nb++) {
        float* d = acc[nb];
        int c0 = mh + rr, k0 = nk + nb * 8 + c2;
        Ts[k0 * 129 + c0] = d[0];
        Ts[(k0 + 1) * 129 + c0] = d[1];
        Ts[k0 * 129 + c0 + 8] = d[2];
        Ts[(k0 + 1) * 129 + c0 + 8] = d[3];
    }
    __syncthreads();
    {
        int cc2 = t & 127, kq = t >> 7;
        float* vb = g_vlad + ((size_t)n * KK) * CC + cb;
        const float* wrow = w + (size_t)(cb + cc2) * KK;
#pragma unroll
        for (int r = 0; r < 16; r++) {
            int k = r * 4 + kq;
            vb[(size_t)k * CC + cc2] = Ts[k * 129 + cc2] - sas[k] * wrow[k];
        }
    }
}

// ---------------- kernel 4: intra-normalize vlad rows -> output ----------------
__global__ __launch_bounds__(128) void kVnorm(float* __restrict__ out) {
    __shared__ float red[4];
    __shared__ float sinv;
    int row = blockIdx.x;
    const float* p = g_vlad + (size_t)row * CC;
    int t = threadIdx.x;
    float v[4];
    float s = 0.f;
#pragma unroll
    for (int j = 0; j < 4; j++) { v[j] = p[t + j * 128]; s += v[j] * v[j]; }
#pragma unroll
    for (int o = 16; o > 0; o >>= 1) s += __shfl_xor_sync(0xffffffffu, s, o);
    int wq = t >> 5;
    if ((t & 31) == 0) red[wq] = s;
    __syncthreads();
    if (t == 0) sinv = 1.f / fmaxf(sqrtf(red[0] + red[1] + red[2] + red[3]), EPSV);
    __syncthreads();
    float inv = sinv;
    float* o = out + (size_t)row * CC;
#pragma unroll
    for (int j = 0; j < 4; j++) o[t + j * 128] = v[j] * inv;
}

extern "C" void kernel_launch(void* const* d_in, const int* in_sizes, int n_in,
                              void* d_out, int out_size) {
    const float* x = (const float*)d_in[0];     // [N,C,H,W]
    const float* w = (const float*)d_in[1];     // [C,K]
    const float* b = (const float*)d_in[2];     // [K]
    float* out = (float*)d_out;

    const size_t VLAD_OFF = 0;
    const size_t SA_OFF = (size_t)NN * KK * CC;
    const size_t FEAT_OFF = SA_OFF + (size_t)NN * KK * HWD;

    cudaFuncSetAttribute(kLogitsFused, cudaFuncAttributeMaxDynamicSharedMemorySize, SMEM_BYTES);
    cudaFuncSetAttribute(kVladMMA, cudaFuncAttributeMaxDynamicSharedMemorySize, SMEM_BYTES);

    kWnorm<<<1, 256>>>(w);
    kLogitsFused<<<dim3(HWD / 128, NN), 512, SMEM_BYTES>>>(x, b, out + FEAT_OFF, out + SA_OFF);
    kVladMMA<<<dim3(CC / 128, NN), 512, SMEM_BYTES>>>(x, w);
    kVnorm<<<NN * KK, 128>>>(out + VLAD_OFF);
}